// round 13
// baseline (speedup 1.0000x reference)
#include <cuda_runtime.h>

#define IN_DIM   8192
#define OUT_DIM  16384
#define TOP_K    327
#define NSLICE   16
#define SLICE    (OUT_DIM / NSLICE)   // 1024
#define NC       257                  // coarse bins, width 32 (covers 0..8223)
#define WHSTRIDE 264                  // padded stride for warp-private copies

// scratch (no allocations allowed). Tickets/flags are reset by the last
// finalizer each launch; g_overlap is zeroed by finalizers; slicecoarse/
// slicefine rows are fully overwritten every launch.
__device__ int g_overlap[OUT_DIM];
__device__ int g_slicecoarse[NSLICE][NC];
__device__ int g_slicefine[NSLICE][32];
__device__ int g_tile_ticket[NSLICE];
__device__ int g_ticket2;
__device__ int g_ticket3;
__device__ int g_CA[2];               // coarse bin C, cumAbove
__device__ int g_Trem[2];             // T, rem
__device__ volatile int g_flag1;
__device__ volatile int g_flag2;
__device__ int g_done;

#define GEMV_TB     256
#define STRIP       128
#define ROW_STRIPS  (IN_DIM / STRIP)        // 64
#define COLS_BLK    (GEMV_TB * 4)           // 1024
#define COL_TILES   (OUT_DIM / COLS_BLK)    // 16

// ---------------------------------------------------------------------------
// k_fused: GEMV + last-block-per-tile top-k selection + emission, one launch.
// ---------------------------------------------------------------------------
__global__ __launch_bounds__(GEMV_TB, 7) void k_fused(const int* __restrict__ x,
                                                      const float* __restrict__ p,
                                                      float* __restrict__ out) {
    __shared__ int srows[STRIP];
    __shared__ int s_wcnt[4];
    __shared__ int s_wh[8 * WHSTRIDE];   // warp-private coarse hists (~8.4 KB)
    __shared__ int s_fine[32];
    __shared__ int s_w[8], s_wab[8], s_w2[8];
    __shared__ int s_fin, s_pub, s_p2, s_tieoff, s_Ts, s_rems;

    const int t    = threadIdx.x;
    const int lane = t & 31;
    const int wid  = t >> 5;
    const int r0   = blockIdx.y * STRIP;
    const int blk  = blockIdx.x;          // column tile == slice index

    // ---- local compaction of this block's 128-row strip (warps 0-3) ----
    int a = 0, myrow = 0;
    unsigned m = 0;
    if (wid < 4) {
        myrow = r0 + t;
        a = (x[myrow] != 0);
        m = __ballot_sync(0xffffffffu, a);
        if (lane == 0) s_wcnt[wid] = __popc(m);
    }
    __syncthreads();
    const int nr = s_wcnt[0] + s_wcnt[1] + s_wcnt[2] + s_wcnt[3];
    if (wid < 4 && a) {
        int off = 0;
        #pragma unroll
        for (int i = 0; i < 4; i++) if (i < wid) off += s_wcnt[i];
        int rank = __popc(m & ((1u << lane) - 1u));
        srows[off + rank] = myrow;
    }
    __syncthreads();

    // ---- binarized accumulation over active rows (BW-bound mainloop) ----
    if (nr > 0) {
        const int col4 = blk * (COLS_BLK / 4) + t;
        const float4* __restrict__ p4 = (const float4*)p;
        const long stride4 = OUT_DIM / 4;

        int c0 = 0, c1 = 0, c2 = 0, c3 = 0;
        int r = 0;
        #pragma unroll 1
        for (; r + 4 <= nr; r += 4) {
            #pragma unroll
            for (int u = 0; u < 4; u++) {
                const int row = srows[r + u];
                const float4 v = __ldg(&p4[(long)row * stride4 + col4]);
                c0 += (v.x > 0.5f);
                c1 += (v.y > 0.5f);
                c2 += (v.z > 0.5f);
                c3 += (v.w > 0.5f);
            }
        }
        for (; r < nr; r++) {
            const int row = srows[r];
            const float4 v = __ldg(&p4[(long)row * stride4 + col4]);
            c0 += (v.x > 0.5f);
            c1 += (v.y > 0.5f);
            c2 += (v.z > 0.5f);
            c3 += (v.w > 0.5f);
        }
        const int cbase = col4 * 4;
        atomicAdd(&g_overlap[cbase + 0], c0);
        atomicAdd(&g_overlap[cbase + 1], c1);
        atomicAdd(&g_overlap[cbase + 2], c2);
        atomicAdd(&g_overlap[cbase + 3], c3);
    }

    // ---- per-tile ticket: 64th block of this column tile becomes finalizer.
    // CRITICAL ordering (threadfence-reduction pattern): every thread's
    // atomics -> fence -> BLOCK BARRIER -> only then t0 takes the ticket.
    __threadfence();
    __syncthreads();                       // <-- the R12 bug was missing this
    if (t == 0)
        s_fin = (atomicAdd(&g_tile_ticket[blk], 1) == ROW_STRIPS - 1);
    __syncthreads();
    if (!s_fin) return;

    // =============== finalizer: slice values are now final ===============
    const int4 vs = __ldcg((const int4*)(g_overlap + blk * SLICE) + t);
    int ov[4] = {vs.x, vs.y, vs.z, vs.w};

    // round 1: warp-private coarse histogram (bins of width 32)
    for (int i = t; i < 8 * WHSTRIDE; i += GEMV_TB) s_wh[i] = 0;
    __syncthreads();
    {
        int* my = s_wh + wid * WHSTRIDE;
        #pragma unroll
        for (int j = 0; j < 4; j++) atomicAdd(&my[ov[j] >> 5], 1);
    }
    __syncthreads();
    {
        int s = 0;
        #pragma unroll
        for (int c = 0; c < 8; c++) s += s_wh[c * WHSTRIDE + t];
        g_slicecoarse[blk][t] = s;
        if (t == 255) {
            int s2 = 0;
            #pragma unroll
            for (int c = 0; c < 8; c++) s2 += s_wh[c * WHSTRIDE + 256];
            g_slicecoarse[blk][256] = s2;
        }
    }
    __threadfence();
    __syncthreads();
    if (t == 0) s_pub = (atomicAdd(&g_ticket2, 1) == NSLICE - 1);
    __syncthreads();

    if (s_pub) {
        // publisher 1: total coarse hist -> suffix scan -> coarse bin C
        int tot = 0, tot256 = 0;
        for (int s = 0; s < NSLICE; s++) tot += __ldcg(&g_slicecoarse[s][t]);
        if (t == 255)
            for (int s = 0; s < NSLICE; s++) tot256 += __ldcg(&g_slicecoarse[s][256]);
        const int loc = tot + tot256;

        int suf = loc;
        #pragma unroll
        for (int off = 1; off < 32; off <<= 1) {
            int v = __shfl_down_sync(0xffffffffu, suf, off);
            if (lane + off < 32) suf += v;
        }
        if (lane == 0) s_w[wid] = suf;
        __syncthreads();
        if (wid == 0) {
            int wv = (lane < 8) ? s_w[lane] : 0;
            int ws = wv;
            #pragma unroll
            for (int off = 1; off < 32; off <<= 1) {
                int v = __shfl_down_sync(0xffffffffu, ws, off);
                if (lane + off < 32) ws += v;
            }
            if (lane < 8) s_wab[lane] = ws - wv;
        }
        __syncthreads();
        const int above = s_wab[wid] + (suf - loc);
        if (above < TOP_K && above + loc >= TOP_K) {
            int C, cum;
            if (t == 255) {
                if (above + tot256 >= TOP_K) { C = 256; cum = above; }
                else                         { C = 255; cum = above + tot256; }
            } else { C = t; cum = above; }
            g_CA[0] = C; g_CA[1] = cum;
            __threadfence();
        }
        __syncthreads();
        if (t == 0) { __threadfence(); g_flag1 = 1; }
    }

    // all finalizers: wait for coarse bin
    if (t == 0) { while (g_flag1 == 0) __nanosleep(64); }
    __syncthreads();
    __threadfence();
    const int C        = __ldcg(&g_CA[0]);
    const int cumAbove = __ldcg(&g_CA[1]);

    // round 2: fine counts inside bin C
    if (t < 32) s_fine[t] = 0;
    __syncthreads();
    #pragma unroll
    for (int j = 0; j < 4; j++) {
        unsigned d = (unsigned)(ov[j] - (C << 5));
        if (d < 32u) atomicAdd(&s_fine[d], 1);
    }
    __syncthreads();
    if (t < 32) g_slicefine[blk][t] = s_fine[t];
    __threadfence();
    __syncthreads();
    if (t == 0) s_p2 = (atomicAdd(&g_ticket3, 1) == NSLICE - 1);
    __syncthreads();

    if (s_p2) {
        if (t < 32) {
            int f = 0;
            for (int s = 0; s < NSLICE; s++) f += __ldcg(&g_slicefine[s][t]);
            s_fine[t] = f;
        }
        __syncthreads();
        if (t == 0) {
            int acc = cumAbove, T = 0, rem = 0;
            for (int i = 31; i >= 0; i--) {
                int h = s_fine[i];
                if (acc < TOP_K && acc + h >= TOP_K) {
                    T = (C << 5) + i; rem = TOP_K - acc; break;
                }
                acc += h;
            }
            g_Trem[0] = T; g_Trem[1] = rem;
            __threadfence();
            g_flag2 = 1;
        }
    }

    // all finalizers: wait for T, rem
    if (t == 0) {
        while (g_flag2 == 0) __nanosleep(64);
        __threadfence();
        s_Ts   = __ldcg(&g_Trem[0]);
        s_rems = __ldcg(&g_Trem[1]);
    }
    __syncthreads();
    const int T   = s_Ts;
    const int rem = s_rems;
    const int d0  = T - (C << 5);

    // cross-slice tie offset: ties at T in slices < blk
    if (wid == 0) {
        int tb = (lane < blk) ? __ldcg(&g_slicefine[lane][d0]) : 0;
        #pragma unroll
        for (int o = 16; o; o >>= 1)
            tb += __shfl_xor_sync(0xffffffffu, tb, o);
        if (lane == 0) s_tieoff = tb;
    }
    __syncthreads();

    // intra-slice tie ranking (ascending index) + emit from registers
    int cnt = 0;
    #pragma unroll
    for (int j = 0; j < 4; j++) cnt += (ov[j] == T);

    int inc = cnt;
    #pragma unroll
    for (int o = 1; o < 32; o <<= 1) {
        int n = __shfl_up_sync(0xffffffffu, inc, o);
        if (lane >= o) inc += n;
    }
    if (lane == 31) s_w2[wid] = inc;
    __syncthreads();
    if (wid == 0) {
        int tot = (lane < 8) ? s_w2[lane] : 0;
        int sv = tot;
        #pragma unroll
        for (int o = 1; o < 32; o <<= 1) {
            int n = __shfl_up_sync(0xffffffffu, sv, o);
            if (lane >= o) sv += n;
        }
        if (lane < 8) s_w2[lane] = sv - tot;
    }
    __syncthreads();
    int run = s_tieoff + s_w2[wid] + (inc - cnt);

    float r[4];
    #pragma unroll
    for (int j = 0; j < 4; j++) {
        int vv = ov[j];
        float o;
        if (vv > T) {
            o = 1.0f;
        } else if (vv == T) {
            o = (run < rem) ? 1.0f : 0.0f;
            run++;
        } else {
            o = 0.0f;
        }
        r[j] = o;
    }
    ((float4*)(out + blk * SLICE))[t] = make_float4(r[0], r[1], r[2], r[3]);

    // reset my slice for the next graph replay
    ((int4*)(g_overlap + blk * SLICE))[t] = make_int4(0, 0, 0, 0);

    // last finalizer resets tickets/flags for the next replay
    if (t == 0) {
        if (atomicAdd(&g_done, 1) == NSLICE - 1) {
            #pragma unroll
            for (int i = 0; i < NSLICE; i++) g_tile_ticket[i] = 0;
            g_ticket2 = 0;
            g_ticket3 = 0;
            g_done    = 0;
            g_flag1   = 0;
            g_flag2   = 0;
        }
    }
}

// ---------------------------------------------------------------------------
extern "C" void kernel_launch(void* const* d_in, const int* in_sizes, int n_in,
                              void* d_out, int out_size) {
    const int*   x = (const int*)d_in[0];   // [1, 8192] int32
    const float* p = (const float*)d_in[1]; // [8192, 16384] float32
    float* out = (float*)d_out;             // [1, 16384] float32

    dim3 grid(COL_TILES, ROW_STRIPS);
    k_fused<<<grid, GEMV_TB>>>(x, p, out);
}

// round 15
// speedup vs baseline: 1.1634x; 1.1634x over previous
#include <cuda_runtime.h>

#define IN_DIM   8192
#define OUT_DIM  16384
#define TOP_K    327
#define NSLICE   16
#define SLICE    (OUT_DIM / NSLICE)   // 1024

// scratch (no allocations allowed). g_pack zero-initialized at load; k_sel
// re-zeroes it and resets the counters every launch (graph-replay invariant).
// Each u64 word packs 4 overlap counters (16 bits each, counts <= 8192:
// partial sums never carry across field boundaries).
__device__ unsigned long long g_pack[OUT_DIM / 4];
__device__ int g_rdy;
__device__ int g_fin;

#define GEMV_TB     256
#define STRIP       128
#define ROW_STRIPS  (IN_DIM / STRIP)        // 64
#define COLS_BLK    (GEMV_TB * 4)           // 1024
#define COL_TILES   (OUT_DIM / COLS_BLK)    // 16

// ---------------------------------------------------------------------------
// k_gemv: overlap[c] += sum over active rows of (p[row][c] > 0.5f)
//   grid = (16 col tiles, 64 row strips), 256 threads. Ballot-compacts its
//   own 128-row strip of x, streams active rows' float4 column slices.
//   Measured ~5.9 TB/s (DRAM roofline). One packed u64 atomic per thread.
// ---------------------------------------------------------------------------
__global__ __launch_bounds__(GEMV_TB, 7) void k_gemv(const int* __restrict__ x,
                                                     const float* __restrict__ p) {
    __shared__ int srows[STRIP];
    __shared__ int s_wcnt[4];

    const int t    = threadIdx.x;
    const int lane = t & 31;
    const int w    = t >> 5;
    const int r0   = blockIdx.y * STRIP;

    int a = 0, myrow = 0;
    unsigned m = 0;
    if (w < 4) {
        myrow = r0 + t;
        a = (x[myrow] != 0);
        m = __ballot_sync(0xffffffffu, a);
        if (lane == 0) s_wcnt[w] = __popc(m);
    }
    __syncthreads();
    const int nr = s_wcnt[0] + s_wcnt[1] + s_wcnt[2] + s_wcnt[3];
    if (w < 4 && a) {
        int off = 0;
        #pragma unroll
        for (int i = 0; i < 4; i++) if (i < w) off += s_wcnt[i];
        int rank = __popc(m & ((1u << lane) - 1u));
        srows[off + rank] = myrow;
    }
    __syncthreads();
    if (nr == 0) return;

    const int col4 = blockIdx.x * GEMV_TB + t;   // float4 index == u64 word index
    const float4* __restrict__ p4 = (const float4*)p;
    const long stride4 = OUT_DIM / 4;

    int c0 = 0, c1 = 0, c2 = 0, c3 = 0;

    int r = 0;
    #pragma unroll 1
    for (; r + 4 <= nr; r += 4) {
        #pragma unroll
        for (int u = 0; u < 4; u++) {
            const int row = srows[r + u];
            const float4 v = __ldg(&p4[(long)row * stride4 + col4]);
            c0 += (v.x > 0.5f);
            c1 += (v.y > 0.5f);
            c2 += (v.z > 0.5f);
            c3 += (v.w > 0.5f);
        }
    }
    for (; r < nr; r++) {
        const int row = srows[r];
        const float4 v = __ldg(&p4[(long)row * stride4 + col4]);
        c0 += (v.x > 0.5f);
        c1 += (v.y > 0.5f);
        c2 += (v.z > 0.5f);
        c3 += (v.w > 0.5f);
    }

    const unsigned lohalf = (unsigned)c0 | ((unsigned)c1 << 16);
    const unsigned hihalf = (unsigned)c2 | ((unsigned)c3 << 16);
    const unsigned long long pv = (unsigned long long)lohalf |
                                  ((unsigned long long)hihalf << 32);
    atomicAdd(&g_pack[col4], pv);
}

// ---------------------------------------------------------------------------
// k_sel: 16 blocks x 1024 threads. Every block redundantly loads the full
// packed overlap (32 KB, 2 int4/thread -> 16 values/thread), selects T/rem
// via coarse(257 x width-32) + fine(32) histograms, computes the jax tie
// rank via a block-wide exclusive scan (thread order == index order), emits
// its own 1024-col slice, then (after a 16-block ready barrier) zeroes its
// slice of g_pack and the last block resets the counters.
// ---------------------------------------------------------------------------
#define SEL_TB    1024
#define NC        257
#define WH_COPIES 8
#define WH_STRIDE 261   // staggered stride: hot bins of copies -> distinct banks

__global__ __launch_bounds__(SEL_TB) void k_sel(float* __restrict__ out) {
    __shared__ int s_wh[WH_COPIES * WH_STRIDE];  // ~8.2 KB
    __shared__ int s_coarse[NC];
    __shared__ int s_fine[32];
    __shared__ int s_w[32], s_wab[32], s_w2[32];
    __shared__ int s_C, s_cum, s_T, s_rem;

    const int t    = threadIdx.x;
    const int lane = t & 31;
    const int wid  = t >> 5;
    const int blk  = blockIdx.x;
    const int copy = wid >> 2;                   // 8 copies, 4 warps each

    // ---- load all 16384 values: 2 int4 = 8 packed ints = 16 values ----
    const int4* gp = (const int4*)g_pack;
    const int4 a0 = __ldg(gp + 2 * t);
    const int4 a1 = __ldg(gp + 2 * t + 1);
    int va[16];
    {
        const int w8[8] = {a0.x, a0.y, a0.z, a0.w, a1.x, a1.y, a1.z, a1.w};
        #pragma unroll
        for (int i = 0; i < 8; i++) {
            va[2 * i + 0] = w8[i] & 0xffff;
            va[2 * i + 1] = (int)((unsigned)w8[i] >> 16);
        }
    }

    // ---- coarse histogram (bins of width 32), 8 bank-staggered copies ----
    for (int i = t; i < WH_COPIES * WH_STRIDE; i += SEL_TB) s_wh[i] = 0;
    if (t < 32) s_fine[t] = 0;
    __syncthreads();
    {
        int* my = s_wh + copy * WH_STRIDE;
        #pragma unroll
        for (int j = 0; j < 16; j++) atomicAdd(&my[va[j] >> 5], 1);
    }
    __syncthreads();
    if (t < NC) {
        int s = 0;
        #pragma unroll
        for (int c = 0; c < WH_COPIES; c++) s += s_wh[c * WH_STRIDE + t];
        s_coarse[t] = s;
    }
    __syncthreads();

    // ---- suffix scan over coarse bins (uniform control flow, no divergent
    //      barriers; threads >= 256 participate with loc = 0) ----
    {
        int c255 = 0, c256 = 0, loc = 0;
        if (t < 256) {
            if (t == 255) {
                c255 = s_coarse[255];
                c256 = s_coarse[256];
                loc  = c255 + c256;
            } else {
                loc = s_coarse[t];
            }
        }

        int suf = loc;
        #pragma unroll
        for (int off = 1; off < 32; off <<= 1) {
            int v = __shfl_down_sync(0xffffffffu, suf, off);
            if (lane + off < 32) suf += v;
        }
        if (lane == 0) s_w[wid] = suf;
        __syncthreads();
        if (wid == 0) {
            int wv = (lane < 8) ? s_w[lane] : 0;
            int ws = wv;
            #pragma unroll
            for (int off = 1; off < 32; off <<= 1) {
                int v = __shfl_down_sync(0xffffffffu, ws, off);
                if (lane + off < 32) ws += v;
            }
            s_wab[lane] = ws - wv;
        }
        __syncthreads();
        if (t < 256) {
            const int above = s_wab[wid] + (suf - loc);
            if (above < TOP_K && above + loc >= TOP_K) {
                int C, cum;
                if (t == 255) {
                    if (above + c256 >= TOP_K) { C = 256; cum = above; }
                    else                       { C = 255; cum = above + c256; }
                } else { C = t; cum = above; }
                s_C = C; s_cum = cum;
            }
        }
    }
    __syncthreads();
    const int C        = s_C;
    const int cumAbove = s_cum;

    // ---- fine histogram inside coarse bin C ----
    #pragma unroll
    for (int j = 0; j < 16; j++) {
        unsigned d = (unsigned)(va[j] - (C << 5));
        if (d < 32u) atomicAdd(&s_fine[d], 1);
    }
    __syncthreads();
    if (t == 0) {
        int acc = cumAbove, T = 0, rem = 0;
        for (int i = 31; i >= 0; i--) {
            int h = s_fine[i];
            if (acc < TOP_K && acc + h >= TOP_K) {
                T = (C << 5) + i; rem = TOP_K - acc; break;
            }
            acc += h;
        }
        s_T = T; s_rem = rem;
    }
    __syncthreads();
    const int T   = s_T;
    const int rem = s_rem;

    // ---- block-wide exclusive scan of tie counts (index order) ----
    int cnt = 0;
    #pragma unroll
    for (int j = 0; j < 16; j++) cnt += (va[j] == T);

    int inc = cnt;
    #pragma unroll
    for (int o = 1; o < 32; o <<= 1) {
        int n = __shfl_up_sync(0xffffffffu, inc, o);
        if (lane >= o) inc += n;
    }
    if (lane == 31) s_w2[wid] = inc;
    __syncthreads();
    if (wid == 0) {
        int tot = s_w2[lane];
        int sv = tot;
        #pragma unroll
        for (int o = 1; o < 32; o <<= 1) {
            int n = __shfl_up_sync(0xffffffffu, sv, o);
            if (lane >= o) sv += n;
        }
        s_w2[lane] = sv - tot;
    }
    __syncthreads();
    int run = s_w2[wid] + (inc - cnt);   // global tie rank of my first value

    // ---- emit my slice (threads 64*blk .. 64*blk+63 own it) ----
    const bool owner = (t >= 64 * blk) && (t < 64 * blk + 64);
    if (owner) {
        float4* o4 = (float4*)out + 4 * t;
        #pragma unroll
        for (int q = 0; q < 4; q++) {
            float r[4];
            #pragma unroll
            for (int j = 0; j < 4; j++) {
                int vv = va[4 * q + j];
                float o;
                if (vv > T) {
                    o = 1.0f;
                } else if (vv == T) {
                    o = (run < rem) ? 1.0f : 0.0f;
                    run++;
                } else {
                    o = 0.0f;
                }
                r[j] = o;
            }
            o4[q] = make_float4(r[0], r[1], r[2], r[3]);
        }
    }

    // ---- ready barrier across the 16 blocks, then zero my slice ----
    // All blocks' loads of g_pack were consumed by their histograms, so once
    // all 16 arrive it is safe to overwrite g_pack. 16 blocks <= 148 SMs:
    // always co-resident, no deadlock.
    __syncthreads();
    if (t == 0) {
        atomicAdd(&g_rdy, 1);
        while (*(volatile int*)&g_rdy < NSLICE) __nanosleep(32);
    }
    __syncthreads();
    if (owner) {
        int4* zp = (int4*)g_pack;
        zp[2 * t]     = make_int4(0, 0, 0, 0);
        zp[2 * t + 1] = make_int4(0, 0, 0, 0);
    }
    if (t == 0) {
        if (atomicAdd(&g_fin, 1) == NSLICE - 1) {
            g_rdy = 0;
            g_fin = 0;
        }
    }
}

// ---------------------------------------------------------------------------
extern "C" void kernel_launch(void* const* d_in, const int* in_sizes, int n_in,
                              void* d_out, int out_size) {
    const int*   x = (const int*)d_in[0];   // [1, 8192] int32
    const float* p = (const float*)d_in[1]; // [8192, 16384] float32
    float* out = (float*)d_out;             // [1, 16384] float32

    dim3 grid(COL_TILES, ROW_STRIPS);
    k_gemv<<<grid, GEMV_TB>>>(x, p);
    k_sel<<<NSLICE, SEL_TB>>>(out);
}